// round 11
// baseline (speedup 1.0000x reference)
#include <cuda_runtime.h>
#include <cuda_fp16.h>
#include <math.h>
#include <stdint.h>

#define N_   50000
#define E_   800000
#define H_   64
#define FE_  32
#define NT_  3
#define ET_  4
#define NEG_ 0.2f

// ---------------- device scratch ----------------
__device__ __align__(16) __half g_e0[E_ * H_];     // ea layer1 (CSR order, fp16)
__device__ __align__(16) __half g_e1[E_ * H_];     // ea layer2
__device__ __align__(16) __half g_ea3[E_ * H_];    // ea layer3
__device__ __align__(16) __half g_pattr[E_ * FE_]; // permuted edge_attr (fp16)
__device__ __align__(16) __half g_h[N_ * H_];      // h (fp16, for gather)
__device__ __align__(16) float g_out[N_ * H_];
__device__ float g_sI[N_];
__device__ float g_sJ[N_];
__device__ float g_exl[E_];                        // exp(logit), CSR order
// CSR  (g_deg starts zero: static init; re-zeroed at end of every run)
__device__ int g_deg[N_];
__device__ int g_off[N_ + 1];
__device__ int g_cur[N_];
__device__ int g_perm[E_];
__device__ int g_psrc[E_];
__device__ int g_pdst[E_];
__device__ int g_petype[E_];

// ---------------- helpers ----------------
__device__ __forceinline__ float lrelu(float x) { return x > 0.f ? x : NEG_ * x; }

__device__ __forceinline__ void mma_f16(float (&c)[4],
                                        uint32_t a0, uint32_t a1, uint32_t a2, uint32_t a3,
                                        uint32_t b0, uint32_t b1) {
    asm volatile(
        "mma.sync.aligned.m16n8k16.row.col.f32.f16.f16.f32 "
        "{%0,%1,%2,%3}, {%4,%5,%6,%7}, {%8,%9}, {%0,%1,%2,%3};"
        : "+f"(c[0]), "+f"(c[1]), "+f"(c[2]), "+f"(c[3])
        : "r"(a0), "r"(a1), "r"(a2), "r"(a3), "r"(b0), "r"(b1));
}

__device__ __forceinline__ uint32_t relu2(uint32_t u) {
    __half2 v = *reinterpret_cast<__half2*>(&u);
    __half2 z = __float2half2_rn(0.f);
    v = __hmax2(v, z);
    return *reinterpret_cast<uint32_t*>(&v);
}

__device__ __forceinline__ uint32_t pack_h2(float a, float b) {
    __half2 h = __floats2half2_rn(a, b);
    return *reinterpret_cast<uint32_t*>(&h);
}

__device__ __forceinline__ float4 unpack_h4(uint2 u) {
    __half2 p0 = *reinterpret_cast<__half2*>(&u.x);
    __half2 p1 = *reinterpret_cast<__half2*>(&u.y);
    float2 f0 = __half22float2(p0), f1 = __half22float2(p1);
    return make_float4(f0.x, f0.y, f1.x, f1.y);
}

// ---------------- node pass body (shared) ----------------
template <bool RELU>
__device__ __forceinline__ void node_body(
    const float* __restrict__ xin, const int* __restrict__ ntype,
    const float* __restrict__ bhl, const float* __restrict__ Watt,
    const float4* sW, int n)
{
    int t = ntype[n];
    const float4* b4 = reinterpret_cast<const float4*>(bhl) + t * 16;
    float4 acc[16];
#pragma unroll
    for (int o4 = 0; o4 < 16; o4++) acc[o4] = __ldg(b4 + o4);

    const float4* x4 = reinterpret_cast<const float4*>(xin) + n * 16;
    const float4* W4 = sW + t * 1024;
#pragma unroll 1
    for (int kc = 0; kc < 16; kc++) {
        float4 v4 = x4[kc];
        if (RELU) {
            v4.x = fmaxf(v4.x, 0.f); v4.y = fmaxf(v4.y, 0.f);
            v4.z = fmaxf(v4.z, 0.f); v4.w = fmaxf(v4.w, 0.f);
        }
        float vv[4] = {v4.x, v4.y, v4.z, v4.w};
#pragma unroll
        for (int j = 0; j < 4; j++) {
            float v = vv[j];
            const float4* wr = W4 + (kc * 4 + j) * 16;
#pragma unroll
            for (int o4 = 0; o4 < 16; o4++) {
                float4 w = wr[o4];
                acc[o4].x += v * w.x; acc[o4].y += v * w.y;
                acc[o4].z += v * w.z; acc[o4].w += v * w.w;
            }
        }
    }

    float sI = 0.f, sJ = 0.f;
#pragma unroll
    for (int o4 = 0; o4 < 16; o4++) {
        float4 a = acc[o4];
        sI += a.x * __ldg(Watt + o4 * 4)     + a.y * __ldg(Watt + o4 * 4 + 1)
            + a.z * __ldg(Watt + o4 * 4 + 2) + a.w * __ldg(Watt + o4 * 4 + 3);
        sJ += a.x * __ldg(Watt + 64 + o4 * 4)     + a.y * __ldg(Watt + 64 + o4 * 4 + 1)
            + a.z * __ldg(Watt + 64 + o4 * 4 + 2) + a.w * __ldg(Watt + 64 + o4 * 4 + 3);
    }

    uint32_t* h32 = reinterpret_cast<uint32_t*>(g_h) + (size_t)n * 32;
#pragma unroll
    for (int o4 = 0; o4 < 16; o4++) {
        h32[o4 * 2]     = pack_h2(acc[o4].x, acc[o4].y);
        h32[o4 * 2 + 1] = pack_h2(acc[o4].z, acc[o4].w);
    }
    g_sI[n] = sI;
    g_sJ[n] = sJ;
}

// ---------------- node kernels ----------------
template <bool RELU>
__global__ void __launch_bounds__(128)
node_kernel(const float* __restrict__ xin, const int* __restrict__ ntype,
            const float* __restrict__ Whl, const float* __restrict__ bhl,
            const float* __restrict__ Watt) {
    __shared__ float4 sW[NT_ * H_ * 16];
    for (int i = threadIdx.x; i < NT_ * H_ * 16; i += blockDim.x)
        sW[i] = reinterpret_cast<const float4*>(Whl)[i];
    __syncthreads();
    int n = blockIdx.x * blockDim.x + threadIdx.x;
    if (n >= N_) return;
    node_body<RELU>(xin, ntype, bhl, Watt, sW, n);
}

// layer-1 node pass fused with CSR histogram (independent work, block-split)
__global__ void __launch_bounds__(128)
node1_hist_kernel(const float* __restrict__ xin, const int* __restrict__ ntype,
                  const float* __restrict__ Whl, const float* __restrict__ bhl,
                  const float* __restrict__ Watt, const int* __restrict__ ei,
                  int nodeBlocks) {
    if (blockIdx.x >= nodeBlocks) {
        int e = (blockIdx.x - nodeBlocks) * 128 + threadIdx.x;
        if (e < E_) atomicAdd(&g_deg[ei[E_ + e]], 1);
        return;
    }
    __shared__ float4 sW[NT_ * H_ * 16];
    for (int i = threadIdx.x; i < NT_ * H_ * 16; i += blockDim.x)
        sW[i] = reinterpret_cast<const float4*>(Whl)[i];
    __syncthreads();
    int n = blockIdx.x * blockDim.x + threadIdx.x;
    if (n >= N_) return;
    node_body<false>(xin, ntype, bhl, Watt, sW, n);
}

// ---------------- scan (single block) ----------------
__global__ void scan_kernel() {
    __shared__ int warpsum[32];
    __shared__ int s_carry;
    int tid = threadIdx.x;
    int lane = tid & 31, wid = tid >> 5;
    if (tid == 0) s_carry = 0;
    __syncthreads();
    for (int base = 0; base < N_; base += 1024) {
        int i = base + tid;
        int v = (i < N_) ? g_deg[i] : 0;
        int incl = v;
#pragma unroll
        for (int d = 1; d < 32; d <<= 1) {
            int t = __shfl_up_sync(0xFFFFFFFFu, incl, d);
            if (lane >= d) incl += t;
        }
        if (lane == 31) warpsum[wid] = incl;
        __syncthreads();
        if (wid == 0) {
            int w = warpsum[lane];
#pragma unroll
            for (int d = 1; d < 32; d <<= 1) {
                int t = __shfl_up_sync(0xFFFFFFFFu, w, d);
                if (lane >= d) w += t;
            }
            warpsum[lane] = w;
        }
        __syncthreads();
        int off = s_carry + (wid > 0 ? warpsum[wid - 1] : 0);
        int excl = off + incl - v;
        if (i < N_) { g_off[i] = excl; g_cur[i] = excl; }
        __syncthreads();
        if (tid == 0) s_carry += warpsum[31];
        __syncthreads();
    }
    if (tid == 0) g_off[N_] = s_carry;
}

// ---------------- scatter: perm + meta + attr(fp16) in one pass ----------------
__global__ void scatter_all_kernel(const int* __restrict__ ei, const int* __restrict__ etype,
                                   const float* __restrict__ eattr) {
    int e = blockIdx.x * blockDim.x + threadIdx.x;
    if (e >= E_) return;
    int dst = ei[E_ + e];
    int pos = atomicAdd(&g_cur[dst], 1);
    g_perm[pos]   = e;
    g_psrc[pos]   = ei[e];
    g_pdst[pos]   = dst;
    g_petype[pos] = etype[e];
    const float4* src = reinterpret_cast<const float4*>(eattr + (size_t)e * FE_);
    uint4* dp = reinterpret_cast<uint4*>(g_pattr + (size_t)pos * FE_);
#pragma unroll
    for (int t = 0; t < 4; t++) {
        float4 f0 = src[t * 2], f1 = src[t * 2 + 1];
        uint4 u;
        u.x = pack_h2(f0.x, f0.y); u.y = pack_h2(f0.z, f0.w);
        u.z = pack_h2(f1.x, f1.y); u.w = pack_h2(f1.z, f1.w);
        dp[t] = u;
    }
}

// ================= edge pass: persistent fp16 MMA, B in REGISTERS =================
// grid-stride over tiles of 128 edges; B fragments are loaded into registers once
// per block -> mainloop touches no shared memory at all.
template <int IN, bool RELU, bool EHEAD>
__global__ void __launch_bounds__(256, 2)
edge_mma_kernel(const __half* __restrict__ ein,
                const float* __restrict__ Wea,
                const float* __restrict__ Watt, const float* __restrict__ Ete,
                __half* __restrict__ eaout,
                const float* __restrict__ Wec, const float* __restrict__ bec,
                float* __restrict__ eout) {
    constexpr int KB = IN / 16;
    constexpr int NTILES = E_ / 128;
    __shared__ uint32_t sB[KB * 8 * 64];
    __shared__ float sWe[64];
    __shared__ float sEteW[ET_];
    __shared__ float sWec[ET_ * 64];
    __shared__ float sBec[ET_];

    int tid = threadIdx.x;
    for (int i = tid; i < KB * 8 * 64; i += 256) {
        int kbnb = i >> 6;
        int j = i & 63;
        int l = j >> 1;
        int hf = j & 1;
        int kb = kbnb >> 3, nb = kbnb & 7;
        int tg = l & 3, gg = l >> 2;
        int k0 = kb * 16 + 2 * tg + hf * 8;
        int n = nb * 8 + gg;
        sB[i] = pack_h2(Wea[k0 * 64 + n], Wea[(k0 + 1) * 64 + n]);
    }
    if (tid < 64) sWe[tid] = Watt[132 + tid];
    if (tid < ET_) {
        float a = 0.f;
#pragma unroll
        for (int j = 0; j < 4; j++) a += lrelu(Ete[tid * 4 + j]) * Watt[128 + j];
        sEteW[tid] = a;
    }
    if (EHEAD) {
        for (int i = tid; i < ET_ * 64; i += 256) sWec[i] = Wec[i];
        if (tid < ET_) sBec[tid] = bec[tid];
    }
    __syncthreads();

    int warp = tid >> 5, lane = tid & 31;
    int g  = lane >> 2;
    int tg = lane & 3;

    // ---- load B fragments to registers, once ----
    uint2 breg[KB][8];
    {
        const uint2* bf = reinterpret_cast<const uint2*>(sB);
#pragma unroll
        for (int kb = 0; kb < KB; kb++)
#pragma unroll
            for (int nb = 0; nb < 8; nb++)
                breg[kb][nb] = bf[(kb * 8 + nb) * 32 + lane];
    }

    for (int tile = blockIdx.x; tile < NTILES; tile += gridDim.x) {
        int e16 = tile * 128 + warp * 16;
        int er0 = e16 + g;
        int er1 = e16 + g + 8;

        // ---- early meta loads: overlap latency with GEMM ----
        int t0 = g_petype[er0];
        int t1 = g_petype[er1];
        float sij0 = 0.f, sij1 = 0.f;
        int p0 = 0, p1 = 0;
        if (tg == 0) {
            int s0 = g_psrc[er0], d0 = g_pdst[er0];
            int s1 = g_psrc[er1], d1 = g_pdst[er1];
            sij0 = g_sI[d0] + g_sJ[s0];
            sij1 = g_sI[d1] + g_sJ[s1];
            if (EHEAD) { p0 = g_perm[er0]; p1 = g_perm[er1]; }
        }

        float c[8][4];
#pragma unroll
        for (int nb = 0; nb < 8; nb++) {
            c[nb][0] = 0.f; c[nb][1] = 0.f; c[nb][2] = 0.f; c[nb][3] = 0.f;
        }

        const uint32_t* A0 = reinterpret_cast<const uint32_t*>(ein + (size_t)er0 * IN);
        const uint32_t* A1 = reinterpret_cast<const uint32_t*>(ein + (size_t)er1 * IN);

#pragma unroll
        for (int kb = 0; kb < KB; kb++) {
            uint32_t a0 = A0[kb * 8 + tg];
            uint32_t a1 = A1[kb * 8 + tg];
            uint32_t a2 = A0[kb * 8 + tg + 4];
            uint32_t a3 = A1[kb * 8 + tg + 4];
            if (RELU) { a0 = relu2(a0); a1 = relu2(a1); a2 = relu2(a2); a3 = relu2(a3); }
#pragma unroll
            for (int nb = 0; nb < 8; nb++) {
                mma_f16(c[nb], a0, a1, a2, a3, breg[kb][nb].x, breg[kb][nb].y);
            }
        }

        // ---- epilogue ----
        uint32_t* o0 = reinterpret_cast<uint32_t*>(eaout + (size_t)er0 * 64);
        uint32_t* o1 = reinterpret_cast<uint32_t*>(eaout + (size_t)er1 * 64);

        float pre0 = 0.f, pre1 = 0.f, eo0 = 0.f, eo1 = 0.f;
#pragma unroll
        for (int nb = 0; nb < 8; nb++) {
            int col = nb * 8 + tg * 2;
            float x0 = lrelu(c[nb][0]), x1 = lrelu(c[nb][1]);
            float x2 = lrelu(c[nb][2]), x3 = lrelu(c[nb][3]);
            pre0 += x0 * sWe[col] + x1 * sWe[col + 1];
            pre1 += x2 * sWe[col] + x3 * sWe[col + 1];
            if (EHEAD) {
                eo0 += fmaxf(x0, 0.f) * sWec[t0 * 64 + col] + fmaxf(x1, 0.f) * sWec[t0 * 64 + col + 1];
                eo1 += fmaxf(x2, 0.f) * sWec[t1 * 64 + col] + fmaxf(x3, 0.f) * sWec[t1 * 64 + col + 1];
            }
            o0[nb * 4 + tg] = pack_h2(x0, x1);
            o1[nb * 4 + tg] = pack_h2(x2, x3);
        }
        pre0 += __shfl_xor_sync(0xFFFFFFFFu, pre0, 1);
        pre0 += __shfl_xor_sync(0xFFFFFFFFu, pre0, 2);
        pre1 += __shfl_xor_sync(0xFFFFFFFFu, pre1, 1);
        pre1 += __shfl_xor_sync(0xFFFFFFFFu, pre1, 2);
        if (EHEAD) {
            eo0 += __shfl_xor_sync(0xFFFFFFFFu, eo0, 1);
            eo0 += __shfl_xor_sync(0xFFFFFFFFu, eo0, 2);
            eo1 += __shfl_xor_sync(0xFFFFFFFFu, eo1, 1);
            eo1 += __shfl_xor_sync(0xFFFFFFFFu, eo1, 2);
        }

        if (tg == 0) {
            g_exl[er0] = __expf(lrelu(sij0 + pre0 + sEteW[t0]));
            g_exl[er1] = __expf(lrelu(sij1 + pre1 + sEteW[t1]));
            if (EHEAD) {
                eout[p0] = eo0 + sBec[t0];
                eout[p1] = eo1 + sBec[t1];
            }
        }
    }
}

// ================= fused gather + finish (persistent) =================
template <bool HEAD>
__global__ void __launch_bounds__(256)
gather_finish_kernel(const __half* __restrict__ ea, const float* __restrict__ Wlin,
                     const int* __restrict__ ntype,
                     const float* __restrict__ Wnc, const float* __restrict__ bnc,
                     float* __restrict__ dout) {
    __shared__ float sWlin[128 * 64];
    __shared__ float stage[8][128];

    int tid = threadIdx.x;
    if (HEAD) {   // re-zero g_deg for the next graph replay
        for (int gid = blockIdx.x * 256 + tid; gid < N_; gid += gridDim.x * 256)
            g_deg[gid] = 0;
    }
    for (int i = tid; i < 128 * 16; i += 256)
        reinterpret_cast<float4*>(sWlin)[i] = reinterpret_cast<const float4*>(Wlin)[i];
    __syncthreads();

    int warp = tid >> 5, lane = tid & 31;
    bool isEa = lane < 16;
    int sub = isEa ? lane : (lane - 16);

    const uint2* ea2 = reinterpret_cast<const uint2*>(ea);
    const uint2* h2  = reinterpret_cast<const uint2*>(g_h);
    float* st = stage[warp];

    for (int grp = blockIdx.x; grp < N_ / 8; grp += gridDim.x) {
        int n = grp * 8 + warp;
        int beg = g_off[n];
        int end = g_off[n + 1];

        float4 acc = make_float4(0.f, 0.f, 0.f, 0.f);
        float sumex = 0.f;

        int i = beg;
        for (; i + 3 < end; i += 4) {
            float ex0 = g_exl[i],     ex1 = g_exl[i + 1];
            float ex2 = g_exl[i + 2], ex3 = g_exl[i + 3];
            uint2 u0 = isEa ? ea2[(size_t)i * 16 + sub]       : h2[(size_t)g_psrc[i] * 16 + sub];
            uint2 u1 = isEa ? ea2[(size_t)(i + 1) * 16 + sub] : h2[(size_t)g_psrc[i + 1] * 16 + sub];
            uint2 u2 = isEa ? ea2[(size_t)(i + 2) * 16 + sub] : h2[(size_t)g_psrc[i + 2] * 16 + sub];
            uint2 u3 = isEa ? ea2[(size_t)(i + 3) * 16 + sub] : h2[(size_t)g_psrc[i + 3] * 16 + sub];
            float4 v0 = unpack_h4(u0), v1 = unpack_h4(u1);
            float4 v2 = unpack_h4(u2), v3 = unpack_h4(u3);
            sumex += (ex0 + ex1) + (ex2 + ex3);
            acc.x += ex0 * v0.x + ex1 * v1.x + ex2 * v2.x + ex3 * v3.x;
            acc.y += ex0 * v0.y + ex1 * v1.y + ex2 * v2.y + ex3 * v3.y;
            acc.z += ex0 * v0.z + ex1 * v1.z + ex2 * v2.z + ex3 * v3.z;
            acc.w += ex0 * v0.w + ex1 * v1.w + ex2 * v2.w + ex3 * v3.w;
        }
        for (; i < end; i++) {
            float ex = g_exl[i];
            uint2 u = isEa ? ea2[(size_t)i * 16 + sub]
                           : h2[(size_t)g_psrc[i] * 16 + sub];
            float4 v = unpack_h4(u);
            sumex += ex;
            acc.x += ex * v.x; acc.y += ex * v.y;
            acc.z += ex * v.z; acc.w += ex * v.w;
        }

        // stage rows: k 0..63 = ex*h (Wlin[:H]), k 64..127 = ex*ea (Wlin[H:])
        int base = isEa ? (64 + sub * 4) : (sub * 4);
        st[base + 0] = acc.x;
        st[base + 1] = acc.y;
        st[base + 2] = acc.z;
        st[base + 3] = acc.w;
        __syncwarp();

        // both half-warps computed the full sumex; xor-16 then halve keeps it exact
        sumex += __shfl_xor_sync(0xFFFFFFFFu, sumex, 16);
        sumex *= 0.5f;
        float inv = 1.f / (sumex + 1e-16f);

        int o1 = lane, o2 = lane + 32;
        float r1 = 0.f, r2 = 0.f;
#pragma unroll 4
        for (int k = 0; k < 128; k++) {
            float v = st[k];
            r1 += v * sWlin[k * 64 + o1];
            r2 += v * sWlin[k * 64 + o2];
        }
        r1 *= inv; r2 *= inv;

        if (!HEAD) {
            g_out[(size_t)n * 64 + o1] = r1;
            g_out[(size_t)n * 64 + o2] = r2;
        } else {
            int t = ntype[n];
            float p = fmaxf(r1, 0.f) * __ldg(Wnc + t * 64 + o1)
                    + fmaxf(r2, 0.f) * __ldg(Wnc + t * 64 + o2);
#pragma unroll
            for (int d = 16; d > 0; d >>= 1) p += __shfl_xor_sync(0xFFFFFFFFu, p, d);
            if (lane == 0) dout[n] = p + bnc[t];
        }
        __syncwarp();
    }
}

// ================= launcher =================
extern "C" void kernel_launch(void* const* d_in, const int* in_sizes, int n_in,
                              void* d_out, int out_size) {
    const float* x     = (const float*)d_in[0];
    const int*   ei    = (const int*)d_in[1];
    const int*   ntype = (const int*)d_in[2];
    const int*   etype = (const int*)d_in[3];
    const float* eattr = (const float*)d_in[4];

    const float* Whl[3]  = {(const float*)d_in[5],  (const float*)d_in[11], (const float*)d_in[17]};
    const float* bhl[3]  = {(const float*)d_in[6],  (const float*)d_in[12], (const float*)d_in[18]};
    const float* Ete[3]  = {(const float*)d_in[7],  (const float*)d_in[13], (const float*)d_in[19]};
    const float* Wea[3]  = {(const float*)d_in[8],  (const float*)d_in[14], (const float*)d_in[20]};
    const float* Watt[3] = {(const float*)d_in[9],  (const float*)d_in[15], (const float*)d_in[21]};
    const float* Wlin[3] = {(const float*)d_in[10], (const float*)d_in[16], (const float*)d_in[22]};
    const float* Wnc = (const float*)d_in[23];
    const float* bnc = (const float*)d_in[24];
    const float* Wec = (const float*)d_in[25];
    const float* bec = (const float*)d_in[26];

    __half *e0, *e1, *ea3, *pattr;
    float *outBuf;
    cudaGetSymbolAddress((void**)&e0, g_e0);
    cudaGetSymbolAddress((void**)&e1, g_e1);
    cudaGetSymbolAddress((void**)&ea3, g_ea3);
    cudaGetSymbolAddress((void**)&pattr, g_pattr);
    cudaGetSymbolAddress((void**)&outBuf, g_out);

    const int nodeBlocks = (N_ + 127) / 128;           // 391
    const int histBlocks = (E_ + 127) / 128;           // 6250
    const int edgeBlocks = (E_ + 255) / 256;           // 3125
    const int mmaGrid    = 592;                        // grid-stride persistent
    const int gfGrid     = 888;

    float* doutN = (float*)d_out;
    float* doutE = (float*)d_out + N_;

    // (1) layer-1 node transform + CSR histogram, fused
    node1_hist_kernel<<<nodeBlocks + histBlocks, 128>>>(
        x, ntype, Whl[0], bhl[0], Watt[0], ei, nodeBlocks);
    // (2) exclusive scan
    scan_kernel<<<1, 1024>>>();
    // (3) scatter permutation + permuted meta + fp16 attr
    scatter_all_kernel<<<edgeBlocks, 256>>>(ei, etype, eattr);

    // (4) layer-1 edge GEMM   <-- ncu capture slot
    edge_mma_kernel<FE_, false, false><<<mmaGrid, 256>>>(
        pattr, Wea[0], Watt[0], Ete[0], e0, nullptr, nullptr, nullptr);
    gather_finish_kernel<false><<<gfGrid, 256>>>(e0, Wlin[0], nullptr, nullptr, nullptr, nullptr);

    // ---- layer 2 ----
    node_kernel<true><<<nodeBlocks, 128>>>(outBuf, ntype, Whl[1], bhl[1], Watt[1]);
    edge_mma_kernel<H_, true, false><<<mmaGrid, 256>>>(
        e0, Wea[1], Watt[1], Ete[1], e1, nullptr, nullptr, nullptr);
    gather_finish_kernel<false><<<gfGrid, 256>>>(e1, Wlin[1], nullptr, nullptr, nullptr, nullptr);

    // ---- layer 3 ----
    node_kernel<true><<<nodeBlocks, 128>>>(outBuf, ntype, Whl[2], bhl[2], Watt[2]);
    edge_mma_kernel<H_, true, true><<<mmaGrid, 256>>>(
        e1, Wea[2], Watt[2], Ete[2], ea3, Wec, bec, doutE);
    gather_finish_kernel<true><<<gfGrid, 256>>>(ea3, Wlin[2], ntype, Wnc, bnc, doutN);
}

// round 13
// speedup vs baseline: 1.1128x; 1.1128x over previous
#include <cuda_runtime.h>
#include <cuda_fp16.h>
#include <math.h>
#include <stdint.h>

#define N_   50000
#define E_   800000
#define H_   64
#define FE_  32
#define NT_  3
#define ET_  4
#define NEG_ 0.2f
#define NTILES (E_ / 128)

// ---------------- device scratch ----------------
__device__ __align__(16) __half g_e0[E_ * H_];     // ea layer1 (CSR order, fp16)
__device__ __align__(16) __half g_e1[E_ * H_];     // ea layer2
__device__ __align__(16) __half g_ea3[E_ * H_];    // ea layer3
__device__ __align__(16) __half g_pattr[E_ * FE_]; // permuted edge_attr (fp16)
__device__ __align__(16) __half g_h[N_ * H_];      // h (fp16, for gather)
__device__ __align__(16) float g_out[N_ * H_];
__device__ float g_sI[N_];
__device__ float g_sJ[N_];
__device__ float g_pre[3 * E_];                    // softmax-independent logit part
// CSR  (g_deg starts zero: static init; re-zeroed at end of every run)
__device__ int g_deg[N_];
__device__ int g_off[N_ + 1];
__device__ int g_cur[N_];
__device__ int g_perm[E_];
__device__ int g_psrc[E_];
__device__ int g_pdst[E_];
__device__ int g_petype[E_];

// ---------------- helpers ----------------
__device__ __forceinline__ float lrelu(float x) { return x > 0.f ? x : NEG_ * x; }

__device__ __forceinline__ void mma_f16(float (&c)[4],
                                        uint32_t a0, uint32_t a1, uint32_t a2, uint32_t a3,
                                        uint32_t b0, uint32_t b1) {
    asm volatile(
        "mma.sync.aligned.m16n8k16.row.col.f32.f16.f16.f32 "
        "{%0,%1,%2,%3}, {%4,%5,%6,%7}, {%8,%9}, {%0,%1,%2,%3};"
        : "+f"(c[0]), "+f"(c[1]), "+f"(c[2]), "+f"(c[3])
        : "r"(a0), "r"(a1), "r"(a2), "r"(a3), "r"(b0), "r"(b1));
}

__device__ __forceinline__ uint32_t pack_h2(float a, float b) {
    __half2 h = __floats2half2_rn(a, b);
    return *reinterpret_cast<uint32_t*>(&h);
}

__device__ __forceinline__ float4 unpack_h4(uint2 u) {
    __half2 p0 = *reinterpret_cast<__half2*>(&u.x);
    __half2 p1 = *reinterpret_cast<__half2*>(&u.y);
    float2 f0 = __half22float2(p0), f1 = __half22float2(p1);
    return make_float4(f0.x, f0.y, f1.x, f1.y);
}

// ---------------- node pass body (shared) ----------------
template <bool RELU>
__device__ __forceinline__ void node_body(
    const float* __restrict__ xin, const int* __restrict__ ntype,
    const float* __restrict__ bhl, const float* __restrict__ Watt,
    const float4* sW, int n)
{
    int t = ntype[n];
    const float4* b4 = reinterpret_cast<const float4*>(bhl) + t * 16;
    float4 acc[16];
#pragma unroll
    for (int o4 = 0; o4 < 16; o4++) acc[o4] = __ldg(b4 + o4);

    const float4* x4 = reinterpret_cast<const float4*>(xin) + n * 16;
    const float4* W4 = sW + t * 1024;
#pragma unroll 1
    for (int kc = 0; kc < 16; kc++) {
        float4 v4 = x4[kc];
        if (RELU) {
            v4.x = fmaxf(v4.x, 0.f); v4.y = fmaxf(v4.y, 0.f);
            v4.z = fmaxf(v4.z, 0.f); v4.w = fmaxf(v4.w, 0.f);
        }
        float vv[4] = {v4.x, v4.y, v4.z, v4.w};
#pragma unroll
        for (int j = 0; j < 4; j++) {
            float v = vv[j];
            const float4* wr = W4 + (kc * 4 + j) * 16;
#pragma unroll
            for (int o4 = 0; o4 < 16; o4++) {
                float4 w = wr[o4];
                acc[o4].x += v * w.x; acc[o4].y += v * w.y;
                acc[o4].z += v * w.z; acc[o4].w += v * w.w;
            }
        }
    }

    float sI = 0.f, sJ = 0.f;
#pragma unroll
    for (int o4 = 0; o4 < 16; o4++) {
        float4 a = acc[o4];
        sI += a.x * __ldg(Watt + o4 * 4)     + a.y * __ldg(Watt + o4 * 4 + 1)
            + a.z * __ldg(Watt + o4 * 4 + 2) + a.w * __ldg(Watt + o4 * 4 + 3);
        sJ += a.x * __ldg(Watt + 64 + o4 * 4)     + a.y * __ldg(Watt + 64 + o4 * 4 + 1)
            + a.z * __ldg(Watt + 64 + o4 * 4 + 2) + a.w * __ldg(Watt + 64 + o4 * 4 + 3);
    }

    uint32_t* h32 = reinterpret_cast<uint32_t*>(g_h) + (size_t)n * 32;
#pragma unroll
    for (int o4 = 0; o4 < 16; o4++) {
        h32[o4 * 2]     = pack_h2(acc[o4].x, acc[o4].y);
        h32[o4 * 2 + 1] = pack_h2(acc[o4].z, acc[o4].w);
    }
    g_sI[n] = sI;
    g_sJ[n] = sJ;
}

// ---------------- node kernels ----------------
template <bool RELU>
__global__ void __launch_bounds__(128)
node_kernel(const float* __restrict__ xin, const int* __restrict__ ntype,
            const float* __restrict__ Whl, const float* __restrict__ bhl,
            const float* __restrict__ Watt) {
    __shared__ float4 sW[NT_ * H_ * 16];
    for (int i = threadIdx.x; i < NT_ * H_ * 16; i += blockDim.x)
        sW[i] = reinterpret_cast<const float4*>(Whl)[i];
    __syncthreads();
    int n = blockIdx.x * blockDim.x + threadIdx.x;
    if (n >= N_) return;
    node_body<RELU>(xin, ntype, bhl, Watt, sW, n);
}

__global__ void __launch_bounds__(128)
node1_hist_kernel(const float* __restrict__ xin, const int* __restrict__ ntype,
                  const float* __restrict__ Whl, const float* __restrict__ bhl,
                  const float* __restrict__ Watt, const int* __restrict__ ei,
                  int nodeBlocks) {
    if (blockIdx.x >= nodeBlocks) {
        int e = (blockIdx.x - nodeBlocks) * 128 + threadIdx.x;
        if (e < E_) atomicAdd(&g_deg[ei[E_ + e]], 1);
        return;
    }
    __shared__ float4 sW[NT_ * H_ * 16];
    for (int i = threadIdx.x; i < NT_ * H_ * 16; i += blockDim.x)
        sW[i] = reinterpret_cast<const float4*>(Whl)[i];
    __syncthreads();
    int n = blockIdx.x * blockDim.x + threadIdx.x;
    if (n >= N_) return;
    node_body<false>(xin, ntype, bhl, Watt, sW, n);
}

// ---------------- scan (single block) ----------------
__global__ void scan_kernel() {
    __shared__ int warpsum[32];
    __shared__ int s_carry;
    int tid = threadIdx.x;
    int lane = tid & 31, wid = tid >> 5;
    if (tid == 0) s_carry = 0;
    __syncthreads();
    for (int base = 0; base < N_; base += 1024) {
        int i = base + tid;
        int v = (i < N_) ? g_deg[i] : 0;
        int incl = v;
#pragma unroll
        for (int d = 1; d < 32; d <<= 1) {
            int t = __shfl_up_sync(0xFFFFFFFFu, incl, d);
            if (lane >= d) incl += t;
        }
        if (lane == 31) warpsum[wid] = incl;
        __syncthreads();
        if (wid == 0) {
            int w = warpsum[lane];
#pragma unroll
            for (int d = 1; d < 32; d <<= 1) {
                int t = __shfl_up_sync(0xFFFFFFFFu, w, d);
                if (lane >= d) w += t;
            }
            warpsum[lane] = w;
        }
        __syncthreads();
        int off = s_carry + (wid > 0 ? warpsum[wid - 1] : 0);
        int excl = off + incl - v;
        if (i < N_) { g_off[i] = excl; g_cur[i] = excl; }
        __syncthreads();
        if (tid == 0) s_carry += warpsum[31];
        __syncthreads();
    }
    if (tid == 0) g_off[N_] = s_carry;
}

// ---------------- scatter: perm + meta + attr(fp16) in one pass ----------------
__global__ void scatter_all_kernel(const int* __restrict__ ei, const int* __restrict__ etype,
                                   const float* __restrict__ eattr) {
    int e = blockIdx.x * blockDim.x + threadIdx.x;
    if (e >= E_) return;
    int dst = ei[E_ + e];
    int pos = atomicAdd(&g_cur[dst], 1);
    g_perm[pos]   = e;
    g_psrc[pos]   = ei[e];
    g_pdst[pos]   = dst;
    g_petype[pos] = etype[e];
    const float4* src = reinterpret_cast<const float4*>(eattr + (size_t)e * FE_);
    uint4* dp = reinterpret_cast<uint4*>(g_pattr + (size_t)pos * FE_);
#pragma unroll
    for (int t = 0; t < 4; t++) {
        float4 f0 = src[t * 2], f1 = src[t * 2 + 1];
        uint4 u;
        u.x = pack_h2(f0.x, f0.y); u.y = pack_h2(f0.z, f0.w);
        u.z = pack_h2(f1.x, f1.y); u.w = pack_h2(f1.z, f1.w);
        dp[t] = u;
    }
}

// ================= MEGA edge pass: 3 chained fp16 GEMMs, ea in registers ======
// C-fragment layout of m16n8k16 == A-fragment layout, so ea_l feeds GEMM_{l+1}
// with a pure register repack (relu). etw is added ONCE, post-reduction (fix).
#define PA_ 20    // attr stage row stride (words)
#define PS_ 36    // ea stage row stride (words)

__global__ void __launch_bounds__(256, 2)
mega_edge_kernel(const float* __restrict__ Wea1, const float* __restrict__ Wea2,
                 const float* __restrict__ Wea3,
                 const float* __restrict__ Watt1, const float* __restrict__ Watt2,
                 const float* __restrict__ Watt3,
                 const float* __restrict__ Ete1, const float* __restrict__ Ete2,
                 const float* __restrict__ Ete3,
                 const float* __restrict__ Wec, const float* __restrict__ bec,
                 float* __restrict__ eout) {
    __shared__ uint32_t sB[5120];            // B frags: L1@0(1024) L2@1024(2048) L3@3072(2048)
    __shared__ uint32_t sStage[128 * PS_];   // attr / ea staging
    __shared__ float sWe[3][64];
    __shared__ float sEteW[3][ET_];
    __shared__ float sWec[ET_ * 64];
    __shared__ float sBec[ET_];

    int tid = threadIdx.x;
    {
        const float* Ws[3] = {Wea1, Wea2, Wea3};
        const int kbs[3] = {2, 4, 4};
        const int bas[3] = {0, 1024, 3072};
        for (int L = 0; L < 3; L++) {
            int tot = kbs[L] * 8 * 64;
            for (int i = tid; i < tot; i += 256) {
                int kbnb = i >> 6;
                int j = i & 63;
                int l = j >> 1, hf = j & 1;
                int kb = kbnb >> 3, nb = kbnb & 7;
                int tg = l & 3, gg = l >> 2;
                int k0 = kb * 16 + 2 * tg + hf * 8;
                int n = nb * 8 + gg;
                sB[bas[L] + i] = pack_h2(Ws[L][k0 * 64 + n], Ws[L][(k0 + 1) * 64 + n]);
            }
        }
        const float* Wa[3] = {Watt1, Watt2, Watt3};
        const float* Et[3] = {Ete1, Ete2, Ete3};
        for (int L = 0; L < 3; L++) {
            if (tid < 64) sWe[L][tid] = Wa[L][132 + tid];
            if (tid < ET_) {
                float a = 0.f;
#pragma unroll
                for (int j = 0; j < 4; j++) a += lrelu(Et[L][tid * 4 + j]) * Wa[L][128 + j];
                sEteW[L][tid] = a;
            }
        }
        for (int i = tid; i < ET_ * 64; i += 256) sWec[i] = Wec[i];
        if (tid < ET_) sBec[tid] = bec[tid];
    }
    __syncthreads();

    int warp = tid >> 5, lane = tid & 31;
    int g = lane >> 2, tg = lane & 3;
    const uint2* bf = reinterpret_cast<const uint2*>(sB);
    int rowA0 = (warp * 16 + g) * PA_;
    int rowA1 = rowA0 + 8 * PA_;
    int rowS0 = (warp * 16 + g) * PS_;
    int rowS1 = rowS0 + 8 * PS_;

    for (int tile = blockIdx.x; tile < NTILES; tile += gridDim.x) {
        int er0 = tile * 128 + warp * 16 + g;
        int er1 = er0 + 8;
        int t0 = g_petype[er0];
        int t1 = g_petype[er1];
        int p0 = 0, p1 = 0;
        if (tg == 0) { p0 = g_perm[er0]; p1 = g_perm[er1]; }

        // ---- stage attr tile (coalesced uint4) ----
        __syncthreads();   // protect stage from previous tile's readers
        {
            const uint4* src = reinterpret_cast<const uint4*>(g_pattr) + (size_t)tile * 512;
#pragma unroll
            for (int j = 0; j < 2; j++) {
                int slot = j * 256 + tid;
                int r = slot >> 2, q = slot & 3;
                *reinterpret_cast<uint4*>(&sStage[r * PA_ + q * 4]) = src[slot];
            }
        }
        __syncthreads();

        // ---- GEMM1 (K=32) ----
        float c1[8][4];
#pragma unroll
        for (int nb = 0; nb < 8; nb++) { c1[nb][0] = c1[nb][1] = c1[nb][2] = c1[nb][3] = 0.f; }
#pragma unroll
        for (int kb = 0; kb < 2; kb++) {
            uint32_t a0 = sStage[rowA0 + kb * 8 + tg];
            uint32_t a1 = sStage[rowA1 + kb * 8 + tg];
            uint32_t a2 = sStage[rowA0 + kb * 8 + tg + 4];
            uint32_t a3 = sStage[rowA1 + kb * 8 + tg + 4];
#pragma unroll
            for (int nb = 0; nb < 8; nb++) {
                uint2 b = bf[(kb * 8 + nb) * 32 + lane];
                mma_f16(c1[nb], a0, a1, a2, a3, b.x, b.y);
            }
        }

        // ---- ea1 = lrelu(c1): pre1, stage, store ----
        float pr0 = 0.f, pr1 = 0.f;
        __syncthreads();   // attr frag reads done before overwrite
#pragma unroll
        for (int nb = 0; nb < 8; nb++) {
            int col = nb * 8 + tg * 2;
            float x0 = lrelu(c1[nb][0]), x1 = lrelu(c1[nb][1]);
            float x2 = lrelu(c1[nb][2]), x3 = lrelu(c1[nb][3]);
            pr0 += x0 * sWe[0][col] + x1 * sWe[0][col + 1];
            pr1 += x2 * sWe[0][col] + x3 * sWe[0][col + 1];
            sStage[rowS0 + nb * 4 + tg] = pack_h2(x0, x1);
            sStage[rowS1 + nb * 4 + tg] = pack_h2(x2, x3);
        }
        __syncthreads();
        {
            uint4* dst = reinterpret_cast<uint4*>(g_e0) + (size_t)tile * 1024;
#pragma unroll
            for (int j = 0; j < 4; j++) {
                int slot = j * 256 + tid;
                int r = slot >> 3, grp = slot & 7;
                dst[slot] = *reinterpret_cast<uint4*>(&sStage[r * PS_ + grp * 4]);
            }
        }
        pr0 += __shfl_xor_sync(0xFFFFFFFFu, pr0, 1);
        pr0 += __shfl_xor_sync(0xFFFFFFFFu, pr0, 2);
        pr1 += __shfl_xor_sync(0xFFFFFFFFu, pr1, 1);
        pr1 += __shfl_xor_sync(0xFFFFFFFFu, pr1, 2);
        if (tg == 0) {
            g_pre[er0] = pr0 + sEteW[0][t0];   // etw added ONCE (post-reduction)
            g_pre[er1] = pr1 + sEteW[0][t1];
        }

        // ---- GEMM2 (K=64), A = relu(c1) from registers ----
        float c2[8][4];
#pragma unroll
        for (int nb = 0; nb < 8; nb++) { c2[nb][0] = c2[nb][1] = c2[nb][2] = c2[nb][3] = 0.f; }
#pragma unroll
        for (int kb = 0; kb < 4; kb++) {
            uint32_t a0 = pack_h2(fmaxf(c1[2 * kb][0], 0.f),     fmaxf(c1[2 * kb][1], 0.f));
            uint32_t a1 = pack_h2(fmaxf(c1[2 * kb][2], 0.f),     fmaxf(c1[2 * kb][3], 0.f));
            uint32_t a2 = pack_h2(fmaxf(c1[2 * kb + 1][0], 0.f), fmaxf(c1[2 * kb + 1][1], 0.f));
            uint32_t a3 = pack_h2(fmaxf(c1[2 * kb + 1][2], 0.f), fmaxf(c1[2 * kb + 1][3], 0.f));
#pragma unroll
            for (int nb = 0; nb < 8; nb++) {
                uint2 b = bf[512 + (kb * 8 + nb) * 32 + lane];
                mma_f16(c2[nb], a0, a1, a2, a3, b.x, b.y);
            }
        }

        // ---- ea2: pre2, stage, store ----
        pr0 = 0.f; pr1 = 0.f;
        __syncthreads();   // STG1 reads done
#pragma unroll
        for (int nb = 0; nb < 8; nb++) {
            int col = nb * 8 + tg * 2;
            float x0 = lrelu(c2[nb][0]), x1 = lrelu(c2[nb][1]);
            float x2 = lrelu(c2[nb][2]), x3 = lrelu(c2[nb][3]);
            pr0 += x0 * sWe[1][col] + x1 * sWe[1][col + 1];
            pr1 += x2 * sWe[1][col] + x3 * sWe[1][col + 1];
            sStage[rowS0 + nb * 4 + tg] = pack_h2(x0, x1);
            sStage[rowS1 + nb * 4 + tg] = pack_h2(x2, x3);
        }
        __syncthreads();
        {
            uint4* dst = reinterpret_cast<uint4*>(g_e1) + (size_t)tile * 1024;
#pragma unroll
            for (int j = 0; j < 4; j++) {
                int slot = j * 256 + tid;
                int r = slot >> 3, grp = slot & 7;
                dst[slot] = *reinterpret_cast<uint4*>(&sStage[r * PS_ + grp * 4]);
            }
        }
        pr0 += __shfl_xor_sync(0xFFFFFFFFu, pr0, 1);
        pr0 += __shfl_xor_sync(0xFFFFFFFFu, pr0, 2);
        pr1 += __shfl_xor_sync(0xFFFFFFFFu, pr1, 1);
        pr1 += __shfl_xor_sync(0xFFFFFFFFu, pr1, 2);
        if (tg == 0) {
            g_pre[E_ + er0] = pr0 + sEteW[1][t0];
            g_pre[E_ + er1] = pr1 + sEteW[1][t1];
        }

        // ---- GEMM3 (K=64), A = relu(c2) ----
        float c3[8][4];
#pragma unroll
        for (int nb = 0; nb < 8; nb++) { c3[nb][0] = c3[nb][1] = c3[nb][2] = c3[nb][3] = 0.f; }
#pragma unroll
        for (int kb = 0; kb < 4; kb++) {
            uint32_t a0 = pack_h2(fmaxf(c2[2 * kb][0], 0.f),     fmaxf(c2[2 * kb][1], 0.f));
            uint32_t a1 = pack_h2(fmaxf(c2[2 * kb][2], 0.f),     fmaxf(c2[2 * kb][3], 0.f));
            uint32_t a2 = pack_h2(fmaxf(c2[2 * kb + 1][0], 0.f), fmaxf(c2[2 * kb + 1][1], 0.f));
            uint32_t a3 = pack_h2(fmaxf(c2[2 * kb + 1][2], 0.f), fmaxf(c2[2 * kb + 1][3], 0.f));
#pragma unroll
            for (int nb = 0; nb < 8; nb++) {
                uint2 b = bf[1536 + (kb * 8 + nb) * 32 + lane];
                mma_f16(c3[nb], a0, a1, a2, a3, b.x, b.y);
            }
        }

        // ---- ea3: pre3, edge head, stage, store ----
        pr0 = 0.f; pr1 = 0.f;
        float eo0 = 0.f, eo1 = 0.f;
        __syncthreads();   // STG2 reads done
#pragma unroll
        for (int nb = 0; nb < 8; nb++) {
            int col = nb * 8 + tg * 2;
            float x0 = lrelu(c3[nb][0]), x1 = lrelu(c3[nb][1]);
            float x2 = lrelu(c3[nb][2]), x3 = lrelu(c3[nb][3]);
            pr0 += x0 * sWe[2][col] + x1 * sWe[2][col + 1];
            pr1 += x2 * sWe[2][col] + x3 * sWe[2][col + 1];
            eo0 += fmaxf(x0, 0.f) * sWec[t0 * 64 + col] + fmaxf(x1, 0.f) * sWec[t0 * 64 + col + 1];
            eo1 += fmaxf(x2, 0.f) * sWec[t1 * 64 + col] + fmaxf(x3, 0.f) * sWec[t1 * 64 + col + 1];
            sStage[rowS0 + nb * 4 + tg] = pack_h2(x0, x1);
            sStage[rowS1 + nb * 4 + tg] = pack_h2(x2, x3);
        }
        __syncthreads();
        {
            uint4* dst = reinterpret_cast<uint4*>(g_ea3) + (size_t)tile * 1024;
#pragma unroll
            for (int j = 0; j < 4; j++) {
                int slot = j * 256 + tid;
                int r = slot >> 3, grp = slot & 7;
                dst[slot] = *reinterpret_cast<uint4*>(&sStage[r * PS_ + grp * 4]);
            }
        }
        pr0 += __shfl_xor_sync(0xFFFFFFFFu, pr0, 1);
        pr0 += __shfl_xor_sync(0xFFFFFFFFu, pr0, 2);
        pr1 += __shfl_xor_sync(0xFFFFFFFFu, pr1, 1);
        pr1 += __shfl_xor_sync(0xFFFFFFFFu, pr1, 2);
        eo0 += __shfl_xor_sync(0xFFFFFFFFu, eo0, 1);
        eo0 += __shfl_xor_sync(0xFFFFFFFFu, eo0, 2);
        eo1 += __shfl_xor_sync(0xFFFFFFFFu, eo1, 1);
        eo1 += __shfl_xor_sync(0xFFFFFFFFu, eo1, 2);
        if (tg == 0) {
            g_pre[2 * E_ + er0] = pr0 + sEteW[2][t0];
            g_pre[2 * E_ + er1] = pr1 + sEteW[2][t1];
            eout[p0] = eo0 + sBec[t0];
            eout[p1] = eo1 + sBec[t1];
        }
    }
}

// ================= fused gather + finish (persistent) =================
// ex computed inline: exp(lrelu(sI[dst] + sJ[src] + pre[e])); all loads broadcast.
template <bool HEAD>
__global__ void __launch_bounds__(256)
gather_finish_kernel(const __half* __restrict__ ea, const float* __restrict__ pre,
                     const float* __restrict__ Wlin,
                     const int* __restrict__ ntype,
                     const float* __restrict__ Wnc, const float* __restrict__ bnc,
                     float* __restrict__ dout) {
    __shared__ float sWlin[128 * 64];
    __shared__ float stage[8][128];

    int tid = threadIdx.x;
    if (HEAD) {   // re-zero g_deg for the next graph replay
        for (int gid = blockIdx.x * 256 + tid; gid < N_; gid += gridDim.x * 256)
            g_deg[gid] = 0;
    }
    for (int i = tid; i < 128 * 16; i += 256)
        reinterpret_cast<float4*>(sWlin)[i] = reinterpret_cast<const float4*>(Wlin)[i];
    __syncthreads();

    int warp = tid >> 5, lane = tid & 31;
    bool isEa = lane < 16;
    int sub = isEa ? lane : (lane - 16);

    const uint2* ea2 = reinterpret_cast<const uint2*>(ea);
    const uint2* h2  = reinterpret_cast<const uint2*>(g_h);
    float* st = stage[warp];

    for (int grp = blockIdx.x; grp < N_ / 8; grp += gridDim.x) {
        int n = grp * 8 + warp;
        int beg = g_off[n];
        int end = g_off[n + 1];
        float sIn = g_sI[n];

        float4 acc = make_float4(0.f, 0.f, 0.f, 0.f);
        float sumex = 0.f;

        int i = beg;
        for (; i + 3 < end; i += 4) {
            int s0 = g_psrc[i],     s1 = g_psrc[i + 1];
            int s2 = g_psrc[i + 2], s3 = g_psrc[i + 3];
            float ex0 = __expf(lrelu(sIn + g_sJ[s0] + pre[i]));
            float ex1 = __expf(lrelu(sIn + g_sJ[s1] + pre[i + 1]));
            float ex2 = __expf(lrelu(sIn + g_sJ[s2] + pre[i + 2]));
            float ex3 = __expf(lrelu(sIn + g_sJ[s3] + pre[i + 3]));
            uint2 u0 = isEa ? ea2[(size_t)i * 16 + sub]       : h2[(size_t)s0 * 16 + sub];
            uint2 u1 = isEa ? ea2[(size_t)(i + 1) * 16 + sub] : h2[(size_t)s1 * 16 + sub];
            uint2 u2 = isEa ? ea2[(size_t)(i + 2) * 16 + sub] : h2[(size_t)s2 * 16 + sub];
            uint2 u3 = isEa ? ea2[(size_t)(i + 3) * 16 + sub] : h2[(size_t)s3 * 16 + sub];
            float4 v0 = unpack_h4(u0), v1 = unpack_h4(u1);
            float4 v2 = unpack_h4(u2), v3 = unpack_h4(u3);
            sumex += (ex0 + ex1) + (ex2 + ex3);
            acc.x += ex0 * v0.x + ex1 * v1.x + ex2 * v2.x + ex3 * v3.x;
            acc.y += ex0 * v0.y + ex1 * v1.y + ex2 * v2.y + ex3 * v3.y;
            acc.z += ex0 * v0.z + ex1 * v1.z + ex2 * v2.z + ex3 * v3.z;
            acc.w += ex0 * v0.w + ex1 * v1.w + ex2 * v2.w + ex3 * v3.w;
        }
        for (; i < end; i++) {
            int s = g_psrc[i];
            float ex = __expf(lrelu(sIn + g_sJ[s] + pre[i]));
            uint2 u = isEa ? ea2[(size_t)i * 16 + sub] : h2[(size_t)s * 16 + sub];
            float4 v = unpack_h4(u);
            sumex += ex;
            acc.x += ex * v.x; acc.y += ex * v.y;
            acc.z += ex * v.z; acc.w += ex * v.w;
        }

        // stage rows: k 0..63 = ex*h (Wlin[:H]), k 64..127 = ex*ea (Wlin[H:])
        int base = isEa ? (64 + sub * 4) : (sub * 4);
        st[base + 0] = acc.x;
        st[base + 1] = acc.y;
        st[base + 2] = acc.z;
        st[base + 3] = acc.w;
        __syncwarp();

        // both half-warps computed the full sumex; xor-16 then halve keeps it exact
        sumex += __shfl_xor_sync(0xFFFFFFFFu, sumex, 16);
        sumex *= 0.5f;
        float inv = 1.f / (sumex + 1e-16f);

        int o1 = lane, o2 = lane + 32;
        float r1 = 0.f, r2 = 0.f;
#pragma unroll 4
        for (int k = 0; k < 128; k++) {
            float v = st[k];
            r1 += v * sWlin[k * 64 + o1];
            r2 += v * sWlin[k * 64 + o2];
        }
        r1 *= inv; r2 *= inv;

        if (!HEAD) {
            g_out[(size_t)n * 64 + o1] = r1;
            g_out[(size_t)n * 64 + o2] = r2;
        } else {
            int t = ntype[n];
            float p = fmaxf(r1, 0.f) * __ldg(Wnc + t * 64 + o1)
                    + fmaxf(r2, 0.f) * __ldg(Wnc + t * 64 + o2);
#pragma unroll
            for (int d = 16; d > 0; d >>= 1) p += __shfl_xor_sync(0xFFFFFFFFu, p, d);
            if (lane == 0) dout[n] = p + bnc[t];
        }
        __syncwarp();
    }
}

// ================= launcher =================
extern "C" void kernel_launch(void* const* d_in, const int* in_sizes, int n_in,
                              void* d_out, int out_size) {
    const float* x     = (const float*)d_in[0];
    const int*   ei    = (const int*)d_in[1];
    const int*   ntype = (const int*)d_in[2];
    const int*   etype = (const int*)d_in[3];
    const float* eattr = (const float*)d_in[4];

    const float* Whl[3]  = {(const float*)d_in[5],  (const float*)d_in[11], (const float*)d_in[17]};
    const float* bhl[3]  = {(const float*)d_in[6],  (const float*)d_in[12], (const float*)d_in[18]};
    const float* Ete[3]  = {(const float*)d_in[7],  (const float*)d_in[13], (const float*)d_in[19]};
    const float* Wea[3]  = {(const float*)d_in[8],  (const float*)d_in[14], (const float*)d_in[20]};
    const float* Watt[3] = {(const float*)d_in[9],  (const float*)d_in[15], (const float*)d_in[21]};
    const float* Wlin[3] = {(const float*)d_in[10], (const float*)d_in[16], (const float*)d_in[22]};
    const float* Wnc = (const float*)d_in[23];
    const float* bnc = (const float*)d_in[24];
    const float* Wec = (const float*)d_in[25];
    const float* bec = (const float*)d_in[26];

    __half *e0, *e1, *ea3;
    float *outBuf, *preBuf;
    cudaGetSymbolAddress((void**)&e0, g_e0);
    cudaGetSymbolAddress((void**)&e1, g_e1);
    cudaGetSymbolAddress((void**)&ea3, g_ea3);
    cudaGetSymbolAddress((void**)&outBuf, g_out);
    cudaGetSymbolAddress((void**)&preBuf, g_pre);

    const int nodeBlocks = (N_ + 127) / 128;           // 391
    const int histBlocks = (E_ + 127) / 128;           // 6250
    const int edgeBlocks = (E_ + 255) / 256;           // 3125
    const int megaGrid   = 296;                        // 2/SM persistent
    const int gfGrid     = 888;

    float* doutN = (float*)d_out;
    float* doutE = (float*)d_out + N_;

    // (1) layer-1 node transform + CSR histogram, fused
    node1_hist_kernel<<<nodeBlocks + histBlocks, 128>>>(
        x, ntype, Whl[0], bhl[0], Watt[0], ei, nodeBlocks);
    // (2) exclusive scan
    scan_kernel<<<1, 1024>>>();
    // (3) scatter permutation + permuted meta + fp16 attr
    scatter_all_kernel<<<edgeBlocks, 256>>>(ei, etype, eattr);

    // (4) MEGA: all three edge GEMM chains + pre + edge head   <-- ncu capture slot
    mega_edge_kernel<<<megaGrid, 256>>>(
        Wea[0], Wea[1], Wea[2], Watt[0], Watt[1], Watt[2],
        Ete[0], Ete[1], Ete[2], Wec, bec, doutE);

    // (5..9) per-layer softmax aggregation + node transforms
    gather_finish_kernel<false><<<gfGrid, 256>>>(e0, preBuf, Wlin[0],
                                                 nullptr, nullptr, nullptr, nullptr);
    node_kernel<true><<<nodeBlocks, 128>>>(outBuf, ntype, Whl[1], bhl[1], Watt[1]);
    gather_finish_kernel<false><<<gfGrid, 256>>>(e1, preBuf + E_, Wlin[1],
                                                 nullptr, nullptr, nullptr, nullptr);
    node_kernel<true><<<nodeBlocks, 128>>>(outBuf, ntype, Whl[2], bhl[2], Watt[2]);
    gather_finish_kernel<true><<<gfGrid, 256>>>(ea3, preBuf + 2 * E_, Wlin[2],
                                                ntype, Wnc, bnc, doutN);
}

// round 15
// speedup vs baseline: 1.1559x; 1.0387x over previous
#include <cuda_runtime.h>
#include <cuda_fp16.h>
#include <math.h>
#include <stdint.h>

#define N_   50000
#define E_   800000
#define H_   64
#define FE_  32
#define NT_  3
#define ET_  4
#define NEG_ 0.2f
#define NTILES (E_ / 128)

// ---------------- device scratch ----------------
__device__ __align__(16) __half g_e0[E_ * H_];     // ea layer1 (CSR order, fp16)
__device__ __align__(16) __half g_e1[E_ * H_];     // ea layer2
__device__ __align__(16) __half g_ea3[E_ * H_];    // ea layer3
__device__ __align__(16) __half g_pattr[E_ * FE_]; // permuted edge_attr (fp16)
__device__ __align__(16) __half g_h[N_ * H_];      // h (fp16, for gather)
__device__ __align__(16) float g_out[N_ * H_];
__device__ float g_sI[N_];
__device__ float g_sJ[N_];
__device__ float g_pre[3 * E_];                    // softmax-independent logit part
// CSR  (g_deg starts zero: static init; re-zeroed at end of every run)
__device__ int g_deg[N_];
__device__ int g_off[N_ + 1];
__device__ int g_cur[N_];
__device__ int g_perm[E_];
__device__ int g_psrc[E_];
__device__ int g_petype[E_];

// ---------------- helpers ----------------
__device__ __forceinline__ float lrelu(float x) { return x > 0.f ? x : NEG_ * x; }

__device__ __forceinline__ void mma_f16(float (&c)[4],
                                        uint32_t a0, uint32_t a1, uint32_t a2, uint32_t a3,
                                        uint32_t b0, uint32_t b1) {
    asm volatile(
        "mma.sync.aligned.m16n8k16.row.col.f32.f16.f16.f32 "
        "{%0,%1,%2,%3}, {%4,%5,%6,%7}, {%8,%9}, {%0,%1,%2,%3};"
        : "+f"(c[0]), "+f"(c[1]), "+f"(c[2]), "+f"(c[3])
        : "r"(a0), "r"(a1), "r"(a2), "r"(a3), "r"(b0), "r"(b1));
}

__device__ __forceinline__ uint32_t pack_h2(float a, float b) {
    __half2 h = __floats2half2_rn(a, b);
    return *reinterpret_cast<uint32_t*>(&h);
}

__device__ __forceinline__ float4 unpack_h4(uint2 u) {
    __half2 p0 = *reinterpret_cast<__half2*>(&u.x);
    __half2 p1 = *reinterpret_cast<__half2*>(&u.y);
    float2 f0 = __half22float2(p0), f1 = __half22float2(p1);
    return make_float4(f0.x, f0.y, f1.x, f1.y);
}

// ---------------- node pass body (shared) ----------------
template <bool RELU>
__device__ __forceinline__ void node_body(
    const float* __restrict__ xin, const int* __restrict__ ntype,
    const float* __restrict__ bhl, const float* __restrict__ Watt,
    const float4* sW, int n)
{
    int t = ntype[n];
    const float4* b4 = reinterpret_cast<const float4*>(bhl) + t * 16;
    float4 acc[16];
#pragma unroll
    for (int o4 = 0; o4 < 16; o4++) acc[o4] = __ldg(b4 + o4);

    const float4* x4 = reinterpret_cast<const float4*>(xin) + n * 16;
    const float4* W4 = sW + t * 1024;
#pragma unroll 1
    for (int kc = 0; kc < 16; kc++) {
        float4 v4 = x4[kc];
        if (RELU) {
            v4.x = fmaxf(v4.x, 0.f); v4.y = fmaxf(v4.y, 0.f);
            v4.z = fmaxf(v4.z, 0.f); v4.w = fmaxf(v4.w, 0.f);
        }
        float vv[4] = {v4.x, v4.y, v4.z, v4.w};
#pragma unroll
        for (int j = 0; j < 4; j++) {
            float v = vv[j];
            const float4* wr = W4 + (kc * 4 + j) * 16;
#pragma unroll
            for (int o4 = 0; o4 < 16; o4++) {
                float4 w = wr[o4];
                acc[o4].x += v * w.x; acc[o4].y += v * w.y;
                acc[o4].z += v * w.z; acc[o4].w += v * w.w;
            }
        }
    }

    float sI = 0.f, sJ = 0.f;
#pragma unroll
    for (int o4 = 0; o4 < 16; o4++) {
        float4 a = acc[o4];
        sI += a.x * __ldg(Watt + o4 * 4)     + a.y * __ldg(Watt + o4 * 4 + 1)
            + a.z * __ldg(Watt + o4 * 4 + 2) + a.w * __ldg(Watt + o4 * 4 + 3);
        sJ += a.x * __ldg(Watt + 64 + o4 * 4)     + a.y * __ldg(Watt + 64 + o4 * 4 + 1)
            + a.z * __ldg(Watt + 64 + o4 * 4 + 2) + a.w * __ldg(Watt + 64 + o4 * 4 + 3);
    }

    uint32_t* h32 = reinterpret_cast<uint32_t*>(g_h) + (size_t)n * 32;
#pragma unroll
    for (int o4 = 0; o4 < 16; o4++) {
        h32[o4 * 2]     = pack_h2(acc[o4].x, acc[o4].y);
        h32[o4 * 2 + 1] = pack_h2(acc[o4].z, acc[o4].w);
    }
    g_sI[n] = sI;
    g_sJ[n] = sJ;
}

// ---------------- node kernels ----------------
template <bool RELU>
__global__ void __launch_bounds__(128)
node_kernel(const float* __restrict__ xin, const int* __restrict__ ntype,
            const float* __restrict__ Whl, const float* __restrict__ bhl,
            const float* __restrict__ Watt) {
    __shared__ float4 sW[NT_ * H_ * 16];
    for (int i = threadIdx.x; i < NT_ * H_ * 16; i += blockDim.x)
        sW[i] = reinterpret_cast<const float4*>(Whl)[i];
    __syncthreads();
    int n = blockIdx.x * blockDim.x + threadIdx.x;
    if (n >= N_) return;
    node_body<RELU>(xin, ntype, bhl, Watt, sW, n);
}

__global__ void __launch_bounds__(128)
node1_hist_kernel(const float* __restrict__ xin, const int* __restrict__ ntype,
                  const float* __restrict__ Whl, const float* __restrict__ bhl,
                  const float* __restrict__ Watt, const int* __restrict__ ei,
                  int nodeBlocks) {
    if (blockIdx.x >= nodeBlocks) {
        int e = (blockIdx.x - nodeBlocks) * 128 + threadIdx.x;
        if (e < E_) atomicAdd(&g_deg[ei[E_ + e]], 1);
        return;
    }
    __shared__ float4 sW[NT_ * H_ * 16];
    for (int i = threadIdx.x; i < NT_ * H_ * 16; i += blockDim.x)
        sW[i] = reinterpret_cast<const float4*>(Whl)[i];
    __syncthreads();
    int n = blockIdx.x * blockDim.x + threadIdx.x;
    if (n >= N_) return;
    node_body<false>(xin, ntype, bhl, Watt, sW, n);
}

// ---------------- scan (single block) ----------------
__global__ void scan_kernel() {
    __shared__ int warpsum[32];
    __shared__ int s_carry;
    int tid = threadIdx.x;
    int lane = tid & 31, wid = tid >> 5;
    if (tid == 0) s_carry = 0;
    __syncthreads();
    for (int base = 0; base < N_; base += 1024) {
        int i = base + tid;
        int v = (i < N_) ? g_deg[i] : 0;
        int incl = v;
#pragma unroll
        for (int d = 1; d < 32; d <<= 1) {
            int t = __shfl_up_sync(0xFFFFFFFFu, incl, d);
            if (lane >= d) incl += t;
        }
        if (lane == 31) warpsum[wid] = incl;
        __syncthreads();
        if (wid == 0) {
            int w = warpsum[lane];
#pragma unroll
            for (int d = 1; d < 32; d <<= 1) {
                int t = __shfl_up_sync(0xFFFFFFFFu, w, d);
                if (lane >= d) w += t;
            }
            warpsum[lane] = w;
        }
        __syncthreads();
        int off = s_carry + (wid > 0 ? warpsum[wid - 1] : 0);
        int excl = off + incl - v;
        if (i < N_) { g_off[i] = excl; g_cur[i] = excl; }
        __syncthreads();
        if (tid == 0) s_carry += warpsum[31];
        __syncthreads();
    }
    if (tid == 0) g_off[N_] = s_carry;
}

// ---------------- scatter: perm + meta + attr(fp16) in one pass ----------------
__global__ void scatter_all_kernel(const int* __restrict__ ei, const int* __restrict__ etype,
                                   const float* __restrict__ eattr) {
    int e = blockIdx.x * blockDim.x + threadIdx.x;
    if (e >= E_) return;
    int dst = ei[E_ + e];
    int pos = atomicAdd(&g_cur[dst], 1);
    g_perm[pos]   = e;
    g_psrc[pos]   = ei[e];
    g_petype[pos] = etype[e];
    const float4* src = reinterpret_cast<const float4*>(eattr + (size_t)e * FE_);
    uint4* dp = reinterpret_cast<uint4*>(g_pattr + (size_t)pos * FE_);
#pragma unroll
    for (int t = 0; t < 4; t++) {
        float4 f0 = src[t * 2], f1 = src[t * 2 + 1];
        uint4 u;
        u.x = pack_h2(f0.x, f0.y); u.y = pack_h2(f0.z, f0.w);
        u.z = pack_h2(f1.x, f1.y); u.w = pack_h2(f1.z, f1.w);
        dp[t] = u;
    }
}

// ================= MEGA edge pass: 3 chained fp16 GEMMs, ea in registers ======
// All staging lives in WARP-PRIVATE 576-word regions (both the PA_ attr layout
// and the PS_ ea layout fit inside), so the tile loop needs only __syncwarp.
#define PA_ 20    // attr stage row stride (words); 16 rows = 320 <= 576
#define PS_ 36    // ea stage row stride (words);   16 rows = 576
#define WREG_ (16 * PS_)   // per-warp stage region (576 words)

__global__ void __launch_bounds__(256, 2)
mega_edge_kernel(const float* __restrict__ Wea1, const float* __restrict__ Wea2,
                 const float* __restrict__ Wea3,
                 const float* __restrict__ Watt1, const float* __restrict__ Watt2,
                 const float* __restrict__ Watt3,
                 const float* __restrict__ Ete1, const float* __restrict__ Ete2,
                 const float* __restrict__ Ete3,
                 const float* __restrict__ Wec, const float* __restrict__ bec,
                 float* __restrict__ eout) {
    __shared__ uint32_t sB[5120];            // B frags: L1@0(1024) L2@1024(2048) L3@3072(2048)
    __shared__ uint32_t sStage[8 * WREG_];   // 8 warp-private 576-word regions
    __shared__ float sWe[3][64];
    __shared__ float sEteW[3][ET_];
    __shared__ float sWec[ET_ * 64];
    __shared__ float sBec[ET_];

    int tid = threadIdx.x;
    {
        const float* Ws[3] = {Wea1, Wea2, Wea3};
        const int kbs[3] = {2, 4, 4};
        const int bas[3] = {0, 1024, 3072};
        for (int L = 0; L < 3; L++) {
            int tot = kbs[L] * 8 * 64;
            for (int i = tid; i < tot; i += 256) {
                int kbnb = i >> 6;
                int j = i & 63;
                int l = j >> 1, hf = j & 1;
                int kb = kbnb >> 3, nb = kbnb & 7;
                int tg = l & 3, gg = l >> 2;
                int k0 = kb * 16 + 2 * tg + hf * 8;
                int n = nb * 8 + gg;
                sB[bas[L] + i] = pack_h2(Ws[L][k0 * 64 + n], Ws[L][(k0 + 1) * 64 + n]);
            }
        }
        const float* Wa[3] = {Watt1, Watt2, Watt3};
        const float* Et[3] = {Ete1, Ete2, Ete3};
        for (int L = 0; L < 3; L++) {
            if (tid < 64) sWe[L][tid] = Wa[L][132 + tid];
            if (tid < ET_) {
                float a = 0.f;
#pragma unroll
                for (int j = 0; j < 4; j++) a += lrelu(Et[L][tid * 4 + j]) * Wa[L][128 + j];
                sEteW[L][tid] = a;
            }
        }
        for (int i = tid; i < ET_ * 64; i += 256) sWec[i] = Wec[i];
        if (tid < ET_) sBec[tid] = bec[tid];
    }
    __syncthreads();

    int warp = tid >> 5, lane = tid & 31;
    int g = lane >> 2, tg = lane & 3;
    const uint2* bf = reinterpret_cast<const uint2*>(sB);
    uint32_t* wst = sStage + warp * WREG_;   // warp-private stage base
    int rowA0 = g * PA_;
    int rowA1 = (g + 8) * PA_;
    int rowS0 = g * PS_;
    int rowS1 = (g + 8) * PS_;

    for (int tile = blockIdx.x; tile < NTILES; tile += gridDim.x) {
        int er0 = tile * 128 + warp * 16 + g;
        int er1 = er0 + 8;
        int t0 = g_petype[er0];
        int t1 = g_petype[er1];
        int p0 = 0, p1 = 0;
        if (tg == 0) { p0 = g_perm[er0]; p1 = g_perm[er1]; }

        // ---- per-warp attr staging (coalesced uint4) ----
        {
            const uint4* src = reinterpret_cast<const uint4*>(g_pattr)
                               + (size_t)tile * 512 + warp * 64;
#pragma unroll
            for (int j = 0; j < 2; j++) {
                int slot = j * 32 + lane;
                int r = slot >> 2, q = slot & 3;
                *reinterpret_cast<uint4*>(&wst[r * PA_ + q * 4]) = src[slot];
            }
        }
        __syncwarp();

        // ---- GEMM1 (K=32) ----
        float c1[8][4];
#pragma unroll
        for (int nb = 0; nb < 8; nb++) { c1[nb][0] = c1[nb][1] = c1[nb][2] = c1[nb][3] = 0.f; }
#pragma unroll
        for (int kb = 0; kb < 2; kb++) {
            uint32_t a0 = wst[rowA0 + kb * 8 + tg];
            uint32_t a1 = wst[rowA1 + kb * 8 + tg];
            uint32_t a2 = wst[rowA0 + kb * 8 + tg + 4];
            uint32_t a3 = wst[rowA1 + kb * 8 + tg + 4];
#pragma unroll
            for (int nb = 0; nb < 8; nb++) {
                uint2 b = bf[(kb * 8 + nb) * 32 + lane];
                mma_f16(c1[nb], a0, a1, a2, a3, b.x, b.y);
            }
        }
        __syncwarp();   // A-frag reads done before stage overwrite

        // ---- ea1 = lrelu(c1): pre1, stage, store ----
        float pr0 = 0.f, pr1 = 0.f;
#pragma unroll
        for (int nb = 0; nb < 8; nb++) {
            int col = nb * 8 + tg * 2;
            float x0 = lrelu(c1[nb][0]), x1 = lrelu(c1[nb][1]);
            float x2 = lrelu(c1[nb][2]), x3 = lrelu(c1[nb][3]);
            pr0 += x0 * sWe[0][col] + x1 * sWe[0][col + 1];
            pr1 += x2 * sWe[0][col] + x3 * sWe[0][col + 1];
            wst[rowS0 + nb * 4 + tg] = pack_h2(x0, x1);
            wst[rowS1 + nb * 4 + tg] = pack_h2(x2, x3);
        }
        __syncwarp();
        {
            uint4* dst = reinterpret_cast<uint4*>(g_e0) + (size_t)tile * 1024 + warp * 128;
#pragma unroll
            for (int j = 0; j < 4; j++) {
                int slot = j * 32 + lane;
                int r = slot >> 3, grp = slot & 7;
                dst[slot] = *reinterpret_cast<uint4*>(&wst[r * PS_ + grp * 4]);
            }
        }
        pr0 += __shfl_xor_sync(0xFFFFFFFFu, pr0, 1);
        pr0 += __shfl_xor_sync(0xFFFFFFFFu, pr0, 2);
        pr1 += __shfl_xor_sync(0xFFFFFFFFu, pr1, 1);
        pr1 += __shfl_xor_sync(0xFFFFFFFFu, pr1, 2);
        if (tg == 0) {
            g_pre[er0] = pr0 + sEteW[0][t0];
            g_pre[er1] = pr1 + sEteW[0][t1];
        }

        // ---- GEMM2 (K=64), A = relu(c1) from registers ----
        float c2[8][4];
#pragma unroll
        for (int nb = 0; nb < 8; nb++) { c2[nb][0] = c2[nb][1] = c2[nb][2] = c2[nb][3] = 0.f; }
#pragma unroll
        for (int kb = 0; kb < 4; kb++) {
            uint32_t a0 = pack_h2(fmaxf(c1[2 * kb][0], 0.f),     fmaxf(c1[2 * kb][1], 0.f));
            uint32_t a1 = pack_h2(fmaxf(c1[2 * kb][2], 0.f),     fmaxf(c1[2 * kb][3], 0.f));
            uint32_t a2 = pack_h2(fmaxf(c1[2 * kb + 1][0], 0.f), fmaxf(c1[2 * kb + 1][1], 0.f));
            uint32_t a3 = pack_h2(fmaxf(c1[2 * kb + 1][2], 0.f), fmaxf(c1[2 * kb + 1][3], 0.f));
#pragma unroll
            for (int nb = 0; nb < 8; nb++) {
                uint2 b = bf[512 + (kb * 8 + nb) * 32 + lane];
                mma_f16(c2[nb], a0, a1, a2, a3, b.x, b.y);
            }
        }
        __syncwarp();   // STG1 stage reads done

        // ---- ea2: pre2, stage, store ----
        pr0 = 0.f; pr1 = 0.f;
#pragma unroll
        for (int nb = 0; nb < 8; nb++) {
            int col = nb * 8 + tg * 2;
            float x0 = lrelu(c2[nb][0]), x1 = lrelu(c2[nb][1]);
            float x2 = lrelu(c2[nb][2]), x3 = lrelu(c2[nb][3]);
            pr0 += x0 * sWe[1][col] + x1 * sWe[1][col + 1];
            pr1 += x2 * sWe[1][col] + x3 * sWe[1][col + 1];
            wst[rowS0 + nb * 4 + tg] = pack_h2(x0, x1);
            wst[rowS1 + nb * 4 + tg] = pack_h2(x2, x3);
        }
        __syncwarp();
        {
            uint4* dst = reinterpret_cast<uint4*>(g_e1) + (size_t)tile * 1024 + warp * 128;
#pragma unroll
            for (int j = 0; j < 4; j++) {
                int slot = j * 32 + lane;
                int r = slot >> 3, grp = slot & 7;
                dst[slot] = *reinterpret_cast<uint4*>(&wst[r * PS_ + grp * 4]);
            }
        }
        pr0 += __shfl_xor_sync(0xFFFFFFFFu, pr0, 1);
        pr0 += __shfl_xor_sync(0xFFFFFFFFu, pr0, 2);
        pr1 += __shfl_xor_sync(0xFFFFFFFFu, pr1, 1);
        pr1 += __shfl_xor_sync(0xFFFFFFFFu, pr1, 2);
        if (tg == 0) {
            g_pre[E_ + er0] = pr0 + sEteW[1][t0];
            g_pre[E_ + er1] = pr1 + sEteW[1][t1];
        }

        // ---- GEMM3 (K=64), A = relu(c2) ----
        float c3[8][4];
#pragma unroll
        for (int nb = 0; nb < 8; nb++) { c3[nb][0] = c3[nb][1] = c3[nb][2] = c3[nb][3] = 0.f; }
#pragma unroll
        for (int kb = 0; kb < 4; kb++) {
            uint32_t a0 = pack_h2(fmaxf(c2[2 * kb][0], 0.f),     fmaxf(c2[2 * kb][1], 0.f));
            uint32_t a1 = pack_h2(fmaxf(c2[2 * kb][2], 0.f),     fmaxf(c2[2 * kb][3], 0.f));
            uint32_t a2 = pack_h2(fmaxf(c2[2 * kb + 1][0], 0.f), fmaxf(c2[2 * kb + 1][1], 0.f));
            uint32_t a3 = pack_h2(fmaxf(c2[2 * kb + 1][2], 0.f), fmaxf(c2[2 * kb + 1][3], 0.f));
#pragma unroll
            for (int nb = 0; nb < 8; nb++) {
                uint2 b = bf[1536 + (kb * 8 + nb) * 32 + lane];
                mma_f16(c3[nb], a0, a1, a2, a3, b.x, b.y);
            }
        }
        __syncwarp();   // STG2 stage reads done

        // ---- ea3: pre3, edge head, stage, store ----
        pr0 = 0.f; pr1 = 0.f;
        float eo0 = 0.f, eo1 = 0.f;
#pragma unroll
        for (int nb = 0; nb < 8; nb++) {
            int col = nb * 8 + tg * 2;
            float x0 = lrelu(c3[nb][0]), x1 = lrelu(c3[nb][1]);
            float x2 = lrelu(c3[nb][2]), x3 = lrelu(c3[nb][3]);
            pr0 += x0 * sWe[2][col] + x1 * sWe[2][col + 1];
            pr1 += x2 * sWe[2][col] + x3 * sWe[2][col + 1];
            eo0 += fmaxf(x0, 0.f) * sWec[t0 * 64 + col] + fmaxf(x1, 0.f) * sWec[t0 * 64 + col + 1];
            eo1 += fmaxf(x2, 0.f) * sWec[t1 * 64 + col] + fmaxf(x3, 0.f) * sWec[t1 * 64 + col + 1];
            wst[rowS0 + nb * 4 + tg] = pack_h2(x0, x1);
            wst[rowS1 + nb * 4 + tg] = pack_h2(x2, x3);
        }
        __syncwarp();
        {
            uint4* dst = reinterpret_cast<uint4*>(g_ea3) + (size_t)tile * 1024 + warp * 128;
#pragma unroll
            for (int j = 0; j < 4; j++) {
                int slot = j * 32 + lane;
                int r = slot >> 3, grp = slot & 7;
                dst[slot] = *reinterpret_cast<uint4*>(&wst[r * PS_ + grp * 4]);
            }
        }
        pr0 += __shfl_xor_sync(0xFFFFFFFFu, pr0, 1);
        pr0 += __shfl_xor_sync(0xFFFFFFFFu, pr0, 2);
        pr1 += __shfl_xor_sync(0xFFFFFFFFu, pr1, 1);
        pr1 += __shfl_xor_sync(0xFFFFFFFFu, pr1, 2);
        eo0 += __shfl_xor_sync(0xFFFFFFFFu, eo0, 1);
        eo0 += __shfl_xor_sync(0xFFFFFFFFu, eo0, 2);
        eo1 += __shfl_xor_sync(0xFFFFFFFFu, eo1, 1);
        eo1 += __shfl_xor_sync(0xFFFFFFFFu, eo1, 2);
        if (tg == 0) {
            g_pre[2 * E_ + er0] = pr0 + sEteW[2][t0];
            g_pre[2 * E_ + er1] = pr1 + sEteW[2][t1];
            eout[p0] = eo0 + sBec[t0];
            eout[p1] = eo1 + sBec[t1];
        }
        __syncwarp();   // STG3 stage reads done before next tile's attr staging
    }
}

// ================= fused gather + finish (persistent) =================
template <bool HEAD>
__global__ void __launch_bounds__(256)
gather_finish_kernel(const __half* __restrict__ ea, const float* __restrict__ pre,
                     const float* __restrict__ Wlin,
                     const int* __restrict__ ntype,
                     const float* __restrict__ Wnc, const float* __restrict__ bnc,
                     float* __restrict__ dout) {
    __shared__ float sWlin[128 * 64];
    __shared__ float stage[8][128];

    int tid = threadIdx.x;
    if (HEAD) {   // re-zero g_deg for the next graph replay
        for (int gid = blockIdx.x * 256 + tid; gid < N_; gid += gridDim.x * 256)
            g_deg[gid] = 0;
    }
    for (int i = tid; i < 128 * 16; i += 256)
        reinterpret_cast<float4*>(sWlin)[i] = reinterpret_cast<const float4*>(Wlin)[i];
    __syncthreads();

    int warp = tid >> 5, lane = tid & 31;
    bool isEa = lane < 16;
    int sub = isEa ? lane : (lane - 16);

    const uint2* ea2 = reinterpret_cast<const uint2*>(ea);
    const uint2* h2  = reinterpret_cast<const uint2*>(g_h);
    float* st = stage[warp];

    for (int grp = blockIdx.x; grp < N_ / 8; grp += gridDim.x) {
        int n = grp * 8 + warp;
        int beg = g_off[n];
        int end = g_off[n + 1];
        float sIn = g_sI[n];

        float4 acc = make_float4(0.f, 0.f, 0.f, 0.f);
        float sumex = 0.f;

        int i = beg;
        for (; i + 3 < end; i += 4) {
            int s0 = g_psrc[i],     s1 = g_psrc[i + 1];
            int s2 = g_psrc[i + 2], s3 = g_psrc[i + 3];
            float ex0 = __expf(lrelu(sIn + g_sJ[s0] + pre[i]));
            float ex1 = __expf(lrelu(sIn + g_sJ[s1] + pre[i + 1]));
            float ex2 = __expf(lrelu(sIn + g_sJ[s2] + pre[i + 2]));
            float ex3 = __expf(lrelu(sIn + g_sJ[s3] + pre[i + 3]));
            uint2 u0 = isEa ? ea2[(size_t)i * 16 + sub]       : h2[(size_t)s0 * 16 + sub];
            uint2 u1 = isEa ? ea2[(size_t)(i + 1) * 16 + sub] : h2[(size_t)s1 * 16 + sub];
            uint2 u2 = isEa ? ea2[(size_t)(i + 2) * 16 + sub] : h2[(size_t)s2 * 16 + sub];
            uint2 u3 = isEa ? ea2[(size_t)(i + 3) * 16 + sub] : h2[(size_t)s3 * 16 + sub];
            float4 v0 = unpack_h4(u0), v1 = unpack_h4(u1);
            float4 v2 = unpack_h4(u2), v3 = unpack_h4(u3);
            sumex += (ex0 + ex1) + (ex2 + ex3);
            acc.x += ex0 * v0.x + ex1 * v1.x + ex2 * v2.x + ex3 * v3.x;
            acc.y += ex0 * v0.y + ex1 * v1.y + ex2 * v2.y + ex3 * v3.y;
            acc.z += ex0 * v0.z + ex1 * v1.z + ex2 * v2.z + ex3 * v3.z;
            acc.w += ex0 * v0.w + ex1 * v1.w + ex2 * v2.w + ex3 * v3.w;
        }
        for (; i < end; i++) {
            int s = g_psrc[i];
            float ex = __expf(lrelu(sIn + g_sJ[s] + pre[i]));
            uint2 u = isEa ? ea2[(size_t)i * 16 + sub] : h2[(size_t)s * 16 + sub];
            float4 v = unpack_h4(u);
            sumex += ex;
            acc.x += ex * v.x; acc.y += ex * v.y;
            acc.z += ex * v.z; acc.w += ex * v.w;
        }

        // stage rows: k 0..63 = ex*h (Wlin[:H]), k 64..127 = ex*ea (Wlin[H:])
        int base = isEa ? (64 + sub * 4) : (sub * 4);
        st[base + 0] = acc.x;
        st[base + 1] = acc.y;
        st[base + 2] = acc.z;
        st[base + 3] = acc.w;
        __syncwarp();

        // both half-warps computed the full sumex; xor-16 then halve keeps it exact
        sumex += __shfl_xor_sync(0xFFFFFFFFu, sumex, 16);
        sumex *= 0.5f;
        float inv = 1.f / (sumex + 1e-16f);

        int o1 = lane, o2 = lane + 32;
        float r1 = 0.f, r2 = 0.f;
#pragma unroll 4
        for (int k = 0; k < 128; k++) {
            float v = st[k];
            r1 += v * sWlin[k * 64 + o1];
            r2 += v * sWlin[k * 64 + o2];
        }
        r1 *= inv; r2 *= inv;

        if (!HEAD) {
            g_out[(size_t)n * 64 + o1] = r1;
            g_out[(size_t)n * 64 + o2] = r2;
        } else {
            int t = ntype[n];
            float p = fmaxf(r1, 0.f) * __ldg(Wnc + t * 64 + o1)
                    + fmaxf(r2, 0.f) * __ldg(Wnc + t * 64 + o2);
#pragma unroll
            for (int d = 16; d > 0; d >>= 1) p += __shfl_xor_sync(0xFFFFFFFFu, p, d);
            if (lane == 0) dout[n] = p + bnc[t];
        }
        __syncwarp();
    }
}

// ================= launcher =================
extern "C" void kernel_launch(void* const* d_in, const int* in_sizes, int n_in,
                              void* d_out, int out_size) {
    const float* x     = (const float*)d_in[0];
    const int*   ei    = (const int*)d_in[1];
    const int*   ntype = (const int*)d_in[2];
    const int*   etype = (const int*)d_in[3];
    const float* eattr = (const float*)d_in[4];

    const float* Whl[3]  = {(const float*)d_in[5],  (const float*)d_in[11], (const float*)d_in[17]};
    const float* bhl[3]  = {(const float*)d_in[6],  (const float*)d_in[12], (const float*)d_in[18]};
    const float* Ete[3]  = {(const float*)d_in[7],  (const float*)d_in[13], (const float*)d_in[19]};
    const float* Wea[3]  = {(const float*)d_in[8],  (const float*)d_in[14], (const float*)d_in[20]};
    const float* Watt[3] = {(const float*)d_in[9],  (const float*)d_in[15], (const float*)d_in[21]};
    const float* Wlin[3] = {(const float*)d_in[10], (const float*)d_in[16], (const float*)d_in[22]};
    const float* Wnc = (const float*)d_in[23];
    const float* bnc = (const float*)d_in[24];
    const float* Wec = (const float*)d_in[25];
    const float* bec = (const float*)d_in[26];

    __half *e0, *e1, *ea3;
    float *outBuf, *preBuf;
    cudaGetSymbolAddress((void**)&e0, g_e0);
    cudaGetSymbolAddress((void**)&e1, g_e1);
    cudaGetSymbolAddress((void**)&ea3, g_ea3);
    cudaGetSymbolAddress((void**)&outBuf, g_out);
    cudaGetSymbolAddress((void**)&preBuf, g_pre);

    const int nodeBlocks = (N_ + 127) / 128;           // 391
    const int histBlocks = (E_ + 127) / 128;           // 6250
    const int edgeBlocks = (E_ + 255) / 256;           // 3125
    const int megaGrid   = 296;                        // 2/SM persistent
    const int gfGrid     = 888;

    float* doutN = (float*)d_out;
    float* doutE = (float*)d_out + N_;

    // (1) layer-1 node transform + CSR histogram, fused
    node1_hist_kernel<<<nodeBlocks + histBlocks, 128>>>(
        x, ntype, Whl[0], bhl[0], Watt[0], ei, nodeBlocks);
    // (2) exclusive scan
    scan_kernel<<<1, 1024>>>();
    // (3) scatter permutation + permuted meta + fp16 attr
    scatter_all_kernel<<<edgeBlocks, 256>>>(ei, etype, eattr);

    // (4) MEGA: all three edge GEMM chains + pre + edge head   <-- ncu capture slot
    mega_edge_kernel<<<megaGrid, 256>>>(
        Wea[0], Wea[1], Wea[2], Watt[0], Watt[1], Watt[2],
        Ete[0], Ete[1], Ete[2], Wec, bec, doutE);

    // (5..9) per-layer softmax aggregation + node transforms
    gather_finish_kernel<false><<<gfGrid, 256>>>(e0, preBuf, Wlin[0],
                                                 nullptr, nullptr, nullptr, nullptr);
    node_kernel<true><<<nodeBlocks, 128>>>(outBuf, ntype, Whl[1], bhl[1], Watt[1]);
    gather_finish_kernel<false><<<gfGrid, 256>>>(e1, preBuf + E_, Wlin[1],
                                                 nullptr, nullptr, nullptr, nullptr);
    node_kernel<true><<<nodeBlocks, 128>>>(outBuf, ntype, Whl[2], bhl[2], Watt[2]);
    gather_finish_kernel<true><<<gfGrid, 256>>>(ea3, preBuf + 2 * E_, Wlin[2],
                                                ntype, Wnc, bnc, doutN);
}